// round 1
// baseline (speedup 1.0000x reference)
#include <cuda_runtime.h>
#include <math.h>

// Problem constants (fixed by the dataset)
#define T_TYPES 4
#define U_DIM   10
#define EMB     200
#define DIM_A   20
#define TU      (T_TYPES * U_DIM)      // 40
#define MAX_NSRC 65536
#define MAX_NDST 8192

// Scratch (device globals: allocation-free)
__device__ float g_src_feat[MAX_NSRC * TU];   // [s][t*U+u], 10.5 MB
__device__ float g_agg[MAX_NDST * TU];        // [b][t*U+u], 1.3 MB

// ---------------------------------------------------------------------------
// K0: zero the aggregation buffer
// ---------------------------------------------------------------------------
__global__ void zero_agg_kernel(int n) {
    int i = blockIdx.x * blockDim.x + threadIdx.x;
    if (i < n) g_agg[i] = 0.0f;
}

// ---------------------------------------------------------------------------
// K1: gather node_type_embeddings rows for input_nodes into compact buffer
//     row = 40 floats = 160B = 10 float4
// ---------------------------------------------------------------------------
__global__ void gather_kernel(const int* __restrict__ input_nodes,
                              const float* __restrict__ nte_table,
                              int n_src) {
    int i = blockIdx.x * blockDim.x + threadIdx.x;   // one float4 per thread
    int total = n_src * (TU / 4);                    // n_src * 10
    if (i >= total) return;
    int s = i / (TU / 4);
    int q = i - s * (TU / 4);
    int node = __ldg(&input_nodes[s]);
    const float4* src = reinterpret_cast<const float4*>(nte_table + (size_t)node * TU);
    float4* dst = reinterpret_cast<float4*>(g_src_feat + (size_t)s * TU);
    dst[q] = __ldg(&src[q]);
}

// ---------------------------------------------------------------------------
// K2: per-edge scatter-add (segment_sum).  One thread per (t, e).
// ---------------------------------------------------------------------------
__global__ void edge_kernel(const int* __restrict__ edge_src,
                            const int* __restrict__ edge_dst,
                            int E) {
    int idx = blockIdx.x * blockDim.x + threadIdx.x;
    int total = T_TYPES * E;
    if (idx >= total) return;
    int t = idx / E;
    int e = idx - t * E;
    int s = __ldg(&edge_src[(size_t)t * E + e]);
    int d = __ldg(&edge_dst[(size_t)t * E + e]);
    const float* src = g_src_feat + (size_t)s * TU + t * U_DIM;
    float*       dst = g_agg      + (size_t)d * TU + t * U_DIM;
#pragma unroll
    for (int u = 0; u < U_DIM; u++) {
        atomicAdd(&dst[u], __ldg(&src[u]));
    }
}

// ---------------------------------------------------------------------------
// K3: attention + projection + normalize.  One block per dst node.
// ---------------------------------------------------------------------------
__global__ void __launch_bounds__(256)
out_kernel(const int*   __restrict__ output_nodes,
           const float* __restrict__ node_emb,
           const float* __restrict__ s1,     // [T,U,A]
           const float* __restrict__ s2,     // [T,A,1]
           const float* __restrict__ W,      // [T,U,EMB]
           float* __restrict__ out)          // [B,T,EMB]
{
    int b   = blockIdx.x;
    int tid = threadIdx.x;

    __shared__ float nte_s[TU];
    __shared__ float att_s[T_TYPES];
    __shared__ float comb_s[U_DIM];
    __shared__ float ssq[T_TYPES];

    if (tid < TU)      nte_s[tid] = g_agg[(size_t)b * TU + tid];
    if (tid < T_TYPES) ssq[tid] = 0.0f;
    __syncthreads();

    // attention scores: score[t] = sum_a tanh(sum_u nte[t,u]*s1[t,u,a]) * s2[t,a]
    if (tid < T_TYPES) {
        int t = tid;
        float score = 0.0f;
#pragma unroll
        for (int a = 0; a < DIM_A; a++) {
            float h = 0.0f;
#pragma unroll
            for (int u = 0; u < U_DIM; u++)
                h += nte_s[t * U_DIM + u] * __ldg(&s1[(t * U_DIM + u) * DIM_A + a]);
            score += tanhf(h) * __ldg(&s2[t * DIM_A + a]);
        }
        att_s[t] = score;
    }
    __syncthreads();

    // softmax over T=4 (thread 0)
    if (tid == 0) {
        float m = fmaxf(fmaxf(att_s[0], att_s[1]), fmaxf(att_s[2], att_s[3]));
        float e0 = expf(att_s[0] - m);
        float e1 = expf(att_s[1] - m);
        float e2 = expf(att_s[2] - m);
        float e3 = expf(att_s[3] - m);
        float inv = 1.0f / (e0 + e1 + e2 + e3);
        att_s[0] = e0 * inv; att_s[1] = e1 * inv;
        att_s[2] = e2 * inv; att_s[3] = e3 * inv;
    }
    __syncthreads();

    // combined[u] = sum_t att[t] * nte[t,u]
    if (tid < U_DIM) {
        float c = 0.0f;
#pragma unroll
        for (int t = 0; t < T_TYPES; t++)
            c += att_s[t] * nte_s[t * U_DIM + tid];
        comb_s[tid] = c;
    }
    __syncthreads();

    // load combined to registers (broadcast from smem)
    float c[U_DIM];
#pragma unroll
    for (int u = 0; u < U_DIM; u++) c[u] = comb_s[u];

    int node = __ldg(&output_nodes[b]);
    float base = 0.0f;
    if (tid < EMB) base = __ldg(&node_emb[(size_t)node * EMB + tid]);

    // out[b,t,e] = base[e] + sum_u c[u]*W[t,u,e];  norm over e per (b,t)
    float v[T_TYPES];
#pragma unroll
    for (int t = 0; t < T_TYPES; t++) {
        float val = base;
        if (tid < EMB) {
#pragma unroll
            for (int u = 0; u < U_DIM; u++)
                val += c[u] * __ldg(&W[(size_t)(t * U_DIM + u) * EMB + tid]);
        } else {
            val = 0.0f;
        }
        v[t] = val;
        // reduce val^2 across block into ssq[t]
        float v2 = val * val;
#pragma unroll
        for (int off = 16; off > 0; off >>= 1)
            v2 += __shfl_down_sync(0xffffffffu, v2, off);
        if ((tid & 31) == 0) atomicAdd(&ssq[t], v2);
    }
    __syncthreads();

    if (tid < EMB) {
#pragma unroll
        for (int t = 0; t < T_TYPES; t++) {
            float norm = sqrtf(ssq[t]);
            out[((size_t)b * T_TYPES + t) * EMB + tid] = v[t] / fmaxf(norm, 1e-12f);
        }
    }
}

// ---------------------------------------------------------------------------
// Launch
// ---------------------------------------------------------------------------
extern "C" void kernel_launch(void* const* d_in, const int* in_sizes, int n_in,
                              void* d_out, int out_size) {
    const int*   input_nodes  = (const int*)  d_in[0];
    const int*   output_nodes = (const int*)  d_in[1];
    const int*   edge_src     = (const int*)  d_in[2];
    const int*   edge_dst     = (const int*)  d_in[3];
    const float* node_emb     = (const float*)d_in[4];
    const float* nte_table    = (const float*)d_in[5];
    const float* W            = (const float*)d_in[6];
    const float* s1           = (const float*)d_in[7];
    const float* s2           = (const float*)d_in[8];
    float* out = (float*)d_out;

    int n_src = in_sizes[0];
    int n_dst = in_sizes[1];
    int E     = in_sizes[2] / T_TYPES;

    // K0: zero agg
    {
        int n = n_dst * TU;
        zero_agg_kernel<<<(n + 255) / 256, 256>>>(n);
    }
    // K1: gather
    {
        int n = n_src * (TU / 4);
        gather_kernel<<<(n + 255) / 256, 256>>>(input_nodes, nte_table, n_src);
    }
    // K2: scatter-add over edges
    {
        int n = T_TYPES * E;
        edge_kernel<<<(n + 255) / 256, 256>>>(edge_src, edge_dst, E);
    }
    // K3: attention + projection + normalize
    out_kernel<<<n_dst, 256>>>(output_nodes, node_emb, s1, s2, W, out);
}

// round 2
// speedup vs baseline: 2.3120x; 2.3120x over previous
#include <cuda_runtime.h>
#include <math.h>

// Problem constants (fixed by the dataset)
#define T_TYPES 4
#define U_DIM   10
#define U_PAD   12                     // padded so each (s,t) row is 48B, 16B-aligned
#define EMB     200
#define DIM_A   20
#define TUP     (T_TYPES * U_PAD)      // 48 floats per node
#define MAX_NSRC 65536
#define MAX_NDST 8192
#define B_TILE  32

// Scratch (device globals: allocation-free)
__device__ float g_src_feat[MAX_NSRC * TUP];  // [s][t*U_PAD+u], 12.6 MB
__device__ float g_agg[MAX_NDST * TUP];       // [b][t*U_PAD+u], 1.6 MB

// ---------------------------------------------------------------------------
// K0: zero the aggregation buffer
// ---------------------------------------------------------------------------
__global__ void zero_agg_kernel(int n) {
    int i = blockIdx.x * blockDim.x + threadIdx.x;
    if (i < n) g_agg[i] = 0.0f;
}

// ---------------------------------------------------------------------------
// K1: gather node_type_embeddings rows into compact padded buffer
//     one thread per (s, t): read 10 floats (5 x float2, 8B-aligned), write 12
// ---------------------------------------------------------------------------
__global__ void gather_kernel(const int* __restrict__ input_nodes,
                              const float* __restrict__ nte_table,
                              int n_src) {
    int i = blockIdx.x * blockDim.x + threadIdx.x;
    int total = n_src * T_TYPES;
    if (i >= total) return;
    int s = i >> 2;
    int t = i & 3;
    int node = __ldg(&input_nodes[s]);
    const float2* src = reinterpret_cast<const float2*>(
        nte_table + (size_t)node * (T_TYPES * U_DIM) + t * U_DIM);
    float2* dst = reinterpret_cast<float2*>(
        g_src_feat + (size_t)s * TUP + t * U_PAD);
#pragma unroll
    for (int q = 0; q < 5; q++) dst[q] = __ldg(&src[q]);
    dst[5] = make_float2(0.0f, 0.0f);   // padding
}

// ---------------------------------------------------------------------------
// K2: per-edge scatter-add using vectorized global reductions (sm_90+)
// ---------------------------------------------------------------------------
__device__ __forceinline__ void red_v4(float* p, float4 v) {
    asm volatile("red.global.add.v4.f32 [%0], {%1, %2, %3, %4};"
                 :: "l"(p), "f"(v.x), "f"(v.y), "f"(v.z), "f"(v.w)
                 : "memory");
}
__device__ __forceinline__ void red_v2(float* p, float2 v) {
    asm volatile("red.global.add.v2.f32 [%0], {%1, %2};"
                 :: "l"(p), "f"(v.x), "f"(v.y)
                 : "memory");
}

__global__ void edge_kernel(const int* __restrict__ edge_src,
                            const int* __restrict__ edge_dst,
                            int E) {
    int idx = blockIdx.x * blockDim.x + threadIdx.x;
    int total = T_TYPES * E;
    if (idx >= total) return;
    int t = idx / E;
    int e = idx - t * E;
    int s = __ldg(&edge_src[(size_t)t * E + e]);
    int d = __ldg(&edge_dst[(size_t)t * E + e]);
    const float* src = g_src_feat + (size_t)s * TUP + t * U_PAD;   // 16B-aligned
    float*       dst = g_agg      + (size_t)d * TUP + t * U_PAD;   // 16B-aligned
    float4 a = __ldg(reinterpret_cast<const float4*>(src));
    float4 b = __ldg(reinterpret_cast<const float4*>(src + 4));
    float2 c = __ldg(reinterpret_cast<const float2*>(src + 8));
    red_v4(dst, a);
    red_v4(dst + 4, b);
    red_v2(dst + 8, c);
}

// ---------------------------------------------------------------------------
// K3: attention + projection + normalize.  B_TILE dst nodes per block.
//     W staged in smem (32KB), base rows staged in smem.
// ---------------------------------------------------------------------------
__global__ void __launch_bounds__(256)
out_kernel(const int*   __restrict__ output_nodes,
           const float* __restrict__ node_emb,
           const float* __restrict__ s1,     // [T,U,A]
           const float* __restrict__ s2,     // [T,A,1]
           const float* __restrict__ W,      // [T,U,EMB]
           float* __restrict__ out,          // [B,T,EMB]
           int n_dst)
{
    __shared__ float W_s[T_TYPES * U_DIM * EMB];   // 8000 floats = 32000 B
    __shared__ float base_s[B_TILE][EMB];          // 25600 B
    __shared__ float nte_s[B_TILE][TUP];           // 6144 B
    __shared__ float att_s[B_TILE][T_TYPES];
    __shared__ float comb_s[B_TILE][U_DIM];

    int tid  = threadIdx.x;
    int lane = tid & 31;
    int w    = tid >> 5;                 // warp id, 8 warps
    int b0   = blockIdx.x * B_TILE;

    // --- stage W (2000 float4 loads) ---
    {
        const float4* Wv = reinterpret_cast<const float4*>(W);
        float4* Ws = reinterpret_cast<float4*>(W_s);
        for (int i = tid; i < (T_TYPES * U_DIM * EMB) / 4; i += 256)
            Ws[i] = __ldg(&Wv[i]);
    }
    // --- stage nte (agg rows) ---
    for (int i = tid; i < B_TILE * TUP; i += 256) {
        int j = i / TUP, k = i - j * TUP;
        nte_s[j][k] = (b0 + j < n_dst) ? g_agg[(size_t)(b0 + j) * TUP + k] : 0.0f;
    }
    // --- stage base rows (float4) ---
    for (int i = tid; i < B_TILE * (EMB / 4); i += 256) {
        int j = i / (EMB / 4), q = i - j * (EMB / 4);
        if (b0 + j < n_dst) {
            int node = __ldg(&output_nodes[b0 + j]);
            reinterpret_cast<float4*>(base_s[j])[q] =
                __ldg(reinterpret_cast<const float4*>(node_emb + (size_t)node * EMB) + q);
        }
    }
    __syncthreads();

    // --- phase A: attention + combined; warp w handles nodes w*4 .. w*4+3 ---
#pragma unroll
    for (int jj = 0; jj < 4; jj++) {
        int j = w * 4 + jj;
        float att = 0.0f;
        if (lane < T_TYPES) {
            int t = lane;
            float score = 0.0f;
#pragma unroll
            for (int a = 0; a < DIM_A; a++) {
                float h = 0.0f;
#pragma unroll
                for (int u = 0; u < U_DIM; u++)
                    h += nte_s[j][t * U_PAD + u] * __ldg(&s1[(t * U_DIM + u) * DIM_A + a]);
                score += tanhf(h) * __ldg(&s2[t * DIM_A + a]);
            }
            // softmax over 4 lanes
            float m = score;
            m = fmaxf(m, __shfl_xor_sync(0xFu, m, 1));
            m = fmaxf(m, __shfl_xor_sync(0xFu, m, 2));
            float ex = expf(score - m);
            float sum = ex;
            sum += __shfl_xor_sync(0xFu, sum, 1);
            sum += __shfl_xor_sync(0xFu, sum, 2);
            att = ex / sum;
            att_s[j][t] = att;
        }
        __syncwarp();
        if (lane < U_DIM) {
            float c = 0.0f;
#pragma unroll
            for (int t = 0; t < T_TYPES; t++)
                c += att_s[j][t] * nte_s[j][t * U_PAD + lane];
            comb_s[j][lane] = c;
        }
        __syncwarp();
    }
    __syncthreads();

    // --- phase B: projection + normalize; 128 (j,t) pairs, 16 per warp ---
    for (int p = w; p < B_TILE * T_TYPES; p += 8) {
        int j = p >> 2;
        int t = p & 3;
        if (b0 + j >= n_dst) continue;

        float c[U_DIM];
#pragma unroll
        for (int u = 0; u < U_DIM; u++) c[u] = comb_s[j][u];

        float v[7];
        float ssq = 0.0f;
#pragma unroll
        for (int it = 0; it < 7; it++) {
            int e = lane + it * 32;
            float val = 0.0f;
            if (e < EMB) {
                val = base_s[j][e];
#pragma unroll
                for (int u = 0; u < U_DIM; u++)
                    val += c[u] * W_s[(t * U_DIM + u) * EMB + e];
            }
            v[it] = val;
            ssq += val * val;
        }
        // warp reduce ssq
#pragma unroll
        for (int off = 16; off > 0; off >>= 1)
            ssq += __shfl_xor_sync(0xffffffffu, ssq, off);
        float inv = 1.0f / fmaxf(sqrtf(ssq), 1e-12f);

        float* o = out + ((size_t)(b0 + j) * T_TYPES + t) * EMB;
#pragma unroll
        for (int it = 0; it < 7; it++) {
            int e = lane + it * 32;
            if (e < EMB) o[e] = v[it] * inv;
        }
    }
}

// ---------------------------------------------------------------------------
// Launch
// ---------------------------------------------------------------------------
extern "C" void kernel_launch(void* const* d_in, const int* in_sizes, int n_in,
                              void* d_out, int out_size) {
    const int*   input_nodes  = (const int*)  d_in[0];
    const int*   output_nodes = (const int*)  d_in[1];
    const int*   edge_src     = (const int*)  d_in[2];
    const int*   edge_dst     = (const int*)  d_in[3];
    const float* node_emb     = (const float*)d_in[4];
    const float* nte_table    = (const float*)d_in[5];
    const float* W            = (const float*)d_in[6];
    const float* s1           = (const float*)d_in[7];
    const float* s2           = (const float*)d_in[8];
    float* out = (float*)d_out;

    int n_src = in_sizes[0];
    int n_dst = in_sizes[1];
    int E     = in_sizes[2] / T_TYPES;

    // K0: zero padded agg
    {
        int n = n_dst * TUP;
        zero_agg_kernel<<<(n + 255) / 256, 256>>>(n);
    }
    // K1: gather (one thread per (s,t))
    {
        int n = n_src * T_TYPES;
        gather_kernel<<<(n + 255) / 256, 256>>>(input_nodes, nte_table, n_src);
    }
    // K2: scatter-add over edges (vector reds)
    {
        int n = T_TYPES * E;
        edge_kernel<<<(n + 255) / 256, 256>>>(edge_src, edge_dst, E);
    }
    // K3: attention + projection + normalize
    {
        int blocks = (n_dst + B_TILE - 1) / B_TILE;
        out_kernel<<<blocks, 256>>>(output_nodes, node_emb, s1, s2, W, out, n_dst);
    }
}

// round 3
// speedup vs baseline: 2.7675x; 1.1970x over previous
#include <cuda_runtime.h>
#include <math.h>

// Problem constants (fixed by the dataset)
#define T_TYPES 4
#define U_DIM   10
#define U_PAD   12                     // padded so each (s,t) row is 48B, 16B-aligned
#define EMB     200
#define DIM_A   20
#define TUP     (T_TYPES * U_PAD)      // 48 floats per node
#define MAX_NSRC 65536
#define MAX_NDST 8192
#define NSLICE  7                      // ceil(EMB/32)

// Scratch (device globals: allocation-free)
__device__ float g_src_feat[MAX_NSRC * TUP];  // [s][t*U_PAD+u], 12.6 MB
__device__ float g_agg[MAX_NDST * TUP];       // [b][t*U_PAD+u], 1.6 MB
__device__ float g_comb[MAX_NDST * U_DIM];    // [b][u]

// ---------------------------------------------------------------------------
// K0: zero the aggregation buffer (float4)
// ---------------------------------------------------------------------------
__global__ void zero_agg_kernel(int n4) {
    int i = blockIdx.x * blockDim.x + threadIdx.x;
    if (i < n4) reinterpret_cast<float4*>(g_agg)[i] = make_float4(0.f, 0.f, 0.f, 0.f);
}

// ---------------------------------------------------------------------------
// K1: gather node_type_embeddings rows into compact padded buffer
//     one thread per (s, t): read 10 floats (5 x float2), write 12
// ---------------------------------------------------------------------------
__global__ void gather_kernel(const int* __restrict__ input_nodes,
                              const float* __restrict__ nte_table,
                              int n_src) {
    int i = blockIdx.x * blockDim.x + threadIdx.x;
    int total = n_src * T_TYPES;
    if (i >= total) return;
    int s = i >> 2;
    int t = i & 3;
    int node = __ldg(&input_nodes[s]);
    const float2* src = reinterpret_cast<const float2*>(
        nte_table + (size_t)node * (T_TYPES * U_DIM) + t * U_DIM);
    float2* dst = reinterpret_cast<float2*>(
        g_src_feat + (size_t)s * TUP + t * U_PAD);
#pragma unroll
    for (int q = 0; q < 5; q++) dst[q] = __ldg(&src[q]);
    dst[5] = make_float2(0.0f, 0.0f);   // padding
}

// ---------------------------------------------------------------------------
// K2: per-edge scatter-add using vectorized global reductions (sm_90+)
// ---------------------------------------------------------------------------
__device__ __forceinline__ void red_v4(float* p, float4 v) {
    asm volatile("red.global.add.v4.f32 [%0], {%1, %2, %3, %4};"
                 :: "l"(p), "f"(v.x), "f"(v.y), "f"(v.z), "f"(v.w)
                 : "memory");
}
__device__ __forceinline__ void red_v2(float* p, float2 v) {
    asm volatile("red.global.add.v2.f32 [%0], {%1, %2};"
                 :: "l"(p), "f"(v.x), "f"(v.y)
                 : "memory");
}

__global__ void edge_kernel(const int* __restrict__ edge_src,
                            const int* __restrict__ edge_dst,
                            int E) {
    int idx = blockIdx.x * blockDim.x + threadIdx.x;
    int total = T_TYPES * E;
    if (idx >= total) return;
    int t = idx / E;
    int e = idx - t * E;
    int s = __ldg(&edge_src[(size_t)t * E + e]);
    int d = __ldg(&edge_dst[(size_t)t * E + e]);
    const float* src = g_src_feat + (size_t)s * TUP + t * U_PAD;   // 16B-aligned
    float*       dst = g_agg      + (size_t)d * TUP + t * U_PAD;   // 16B-aligned
    float4 a = __ldg(reinterpret_cast<const float4*>(src));
    float4 b = __ldg(reinterpret_cast<const float4*>(src + 4));
    float2 c = __ldg(reinterpret_cast<const float2*>(src + 8));
    red_v4(dst, a);
    red_v4(dst + 4, b);
    red_v2(dst + 8, c);
}

// ---------------------------------------------------------------------------
// K3a: attention + combine.  One THREAD per dst node.
// ---------------------------------------------------------------------------
__global__ void __launch_bounds__(256)
combine_kernel(const float* __restrict__ s1,    // [T,U,A]
               const float* __restrict__ s2,    // [T,A,1]
               int n_dst)
{
    __shared__ float s1_s[T_TYPES * U_DIM * DIM_A];   // 800 floats
    __shared__ float s2_s[T_TYPES * DIM_A];           // 80 floats

    int tid = threadIdx.x;
    for (int i = tid; i < T_TYPES * U_DIM * DIM_A; i += 256) s1_s[i] = __ldg(&s1[i]);
    if (tid < T_TYPES * DIM_A) s2_s[tid] = __ldg(&s2[tid]);
    __syncthreads();

    int b = blockIdx.x * blockDim.x + tid;
    if (b >= n_dst) return;

    float nte[T_TYPES][U_DIM];
#pragma unroll
    for (int t = 0; t < T_TYPES; t++) {
        const float2* p = reinterpret_cast<const float2*>(
            g_agg + (size_t)b * TUP + t * U_PAD);
#pragma unroll
        for (int q = 0; q < 5; q++) {
            float2 v = p[q];
            nte[t][2 * q] = v.x;
            nte[t][2 * q + 1] = v.y;
        }
    }

    float sc[T_TYPES];
#pragma unroll
    for (int t = 0; t < T_TYPES; t++) {
        float score = 0.0f;
#pragma unroll
        for (int a = 0; a < DIM_A; a++) {
            float h = 0.0f;
#pragma unroll
            for (int u = 0; u < U_DIM; u++)
                h += nte[t][u] * s1_s[(t * U_DIM + u) * DIM_A + a];
            score += tanhf(h) * s2_s[t * DIM_A + a];
        }
        sc[t] = score;
    }
    // softmax over T=4
    float m = fmaxf(fmaxf(sc[0], sc[1]), fmaxf(sc[2], sc[3]));
    float e0 = expf(sc[0] - m), e1 = expf(sc[1] - m);
    float e2 = expf(sc[2] - m), e3 = expf(sc[3] - m);
    float inv = 1.0f / (e0 + e1 + e2 + e3);
    float att[T_TYPES] = {e0 * inv, e1 * inv, e2 * inv, e3 * inv};

#pragma unroll
    for (int u = 0; u < U_DIM; u++) {
        float c = 0.0f;
#pragma unroll
        for (int t = 0; t < T_TYPES; t++) c += att[t] * nte[t][u];
        g_comb[(size_t)b * U_DIM + u] = c;
    }
}

// ---------------------------------------------------------------------------
// K3b: projection + normalize.  One warp per 4 (b) rows, fixed t per block.
//      W[t] slice held in registers (7 slices x 10 u).
// ---------------------------------------------------------------------------
__global__ void __launch_bounds__(256, 2)
project_kernel(const int*   __restrict__ output_nodes,
               const float* __restrict__ node_emb,
               const float* __restrict__ W,      // [T,U,EMB]
               float* __restrict__ out,          // [B,T,EMB]
               int n_dst)
{
    int t    = blockIdx.y;
    int lane = threadIdx.x & 31;
    int w    = threadIdx.x >> 5;          // 8 warps
    int b0   = blockIdx.x * 32 + w * 4;   // 4 rows per warp

    // W registers for this t: Wr[it][u] = W[t][u][it*32+lane]
    float Wr[NSLICE][U_DIM];
#pragma unroll
    for (int it = 0; it < NSLICE; it++) {
        int e = it * 32 + lane;
#pragma unroll
        for (int u = 0; u < U_DIM; u++)
            Wr[it][u] = (e < EMB) ? __ldg(&W[(size_t)(t * U_DIM + u) * EMB + e]) : 0.0f;
    }

#pragma unroll
    for (int jj = 0; jj < 4; jj++) {
        int b = b0 + jj;
        if (b >= n_dst) continue;

        float c[U_DIM];
#pragma unroll
        for (int u = 0; u < U_DIM; u++)
            c[u] = __ldg(&g_comb[(size_t)b * U_DIM + u]);   // broadcast

        int node = __ldg(&output_nodes[b]);
        const float* base = node_emb + (size_t)node * EMB;

        float v[NSLICE];
        float ssq = 0.0f;
#pragma unroll
        for (int it = 0; it < NSLICE; it++) {
            int e = it * 32 + lane;
            float val = 0.0f;
            if (e < EMB) {
                val = __ldg(&base[e]);
#pragma unroll
                for (int u = 0; u < U_DIM; u++)
                    val += c[u] * Wr[it][u];
            }
            v[it] = val;
            ssq += val * val;
        }
#pragma unroll
        for (int off = 16; off > 0; off >>= 1)
            ssq += __shfl_xor_sync(0xffffffffu, ssq, off);
        float inv = 1.0f / fmaxf(sqrtf(ssq), 1e-12f);

        float* o = out + ((size_t)b * T_TYPES + t) * EMB;
#pragma unroll
        for (int it = 0; it < NSLICE; it++) {
            int e = it * 32 + lane;
            if (e < EMB) o[e] = v[it] * inv;
        }
    }
}

// ---------------------------------------------------------------------------
// Launch
// ---------------------------------------------------------------------------
extern "C" void kernel_launch(void* const* d_in, const int* in_sizes, int n_in,
                              void* d_out, int out_size) {
    const int*   input_nodes  = (const int*)  d_in[0];
    const int*   output_nodes = (const int*)  d_in[1];
    const int*   edge_src     = (const int*)  d_in[2];
    const int*   edge_dst     = (const int*)  d_in[3];
    const float* node_emb     = (const float*)d_in[4];
    const float* nte_table    = (const float*)d_in[5];
    const float* W            = (const float*)d_in[6];
    const float* s1           = (const float*)d_in[7];
    const float* s2           = (const float*)d_in[8];
    float* out = (float*)d_out;

    int n_src = in_sizes[0];
    int n_dst = in_sizes[1];
    int E     = in_sizes[2] / T_TYPES;

    // K0: zero padded agg (float4)
    {
        int n4 = (n_dst * TUP) / 4;
        zero_agg_kernel<<<(n4 + 255) / 256, 256>>>(n4);
    }
    // K1: gather (one thread per (s,t))
    {
        int n = n_src * T_TYPES;
        gather_kernel<<<(n + 255) / 256, 256>>>(input_nodes, nte_table, n_src);
    }
    // K2: scatter-add over edges (vector reds)
    {
        int n = T_TYPES * E;
        edge_kernel<<<(n + 255) / 256, 256>>>(edge_src, edge_dst, E);
    }
    // K3a: attention + combine
    combine_kernel<<<(n_dst + 255) / 256, 256>>>(s1, s2, n_dst);
    // K3b: projection + normalize
    {
        dim3 grid((n_dst + 31) / 32, T_TYPES);
        project_kernel<<<grid, 256>>>(output_nodes, node_emb, W, out, n_dst);
    }
}

// round 4
// speedup vs baseline: 3.0568x; 1.1045x over previous
#include <cuda_runtime.h>
#include <math.h>

// Problem constants (fixed by the dataset)
#define T_TYPES 4
#define U_DIM   10
#define U_PAD   12                     // padded so each (s,t) row is 48B, 16B-aligned
#define EMB     200
#define DIM_A   20
#define TUP     (T_TYPES * U_PAD)      // 48 floats per node
#define MAX_NSRC 65536
#define MAX_NDST 8192
#define NSLICE  7                      // ceil(EMB/32)

// Scratch (device globals: allocation-free)
__device__ float g_src_feat[MAX_NSRC * TUP];  // [s][t*U_PAD+u], 12.6 MB
__device__ float g_agg[MAX_NDST * TUP];       // [b][t*U_PAD+u], 1.6 MB
__device__ float g_comb[MAX_NDST * U_DIM];    // [b][u]

// ---------------------------------------------------------------------------
// K1: gather node_type_embeddings rows into compact padded buffer
//     (also zeroes g_agg: disjoint buffer, rides along for free)
// ---------------------------------------------------------------------------
__global__ void gather_kernel(const int* __restrict__ input_nodes,
                              const float* __restrict__ nte_table,
                              int n_src, int n_zero4) {
    int i = blockIdx.x * blockDim.x + threadIdx.x;
    if (i < n_zero4)
        reinterpret_cast<float4*>(g_agg)[i] = make_float4(0.f, 0.f, 0.f, 0.f);
    int total = n_src * T_TYPES;
    if (i >= total) return;
    int s = i >> 2;
    int t = i & 3;
    int node = __ldg(&input_nodes[s]);
    const float2* src = reinterpret_cast<const float2*>(
        nte_table + (size_t)node * (T_TYPES * U_DIM) + t * U_DIM);
    float2* dst = reinterpret_cast<float2*>(
        g_src_feat + (size_t)s * TUP + t * U_PAD);
#pragma unroll
    for (int q = 0; q < 5; q++) dst[q] = __ldg(&src[q]);
    dst[5] = make_float2(0.0f, 0.0f);   // padding
}

// ---------------------------------------------------------------------------
// K2: per-edge scatter-add using vectorized global reductions (sm_90+)
// ---------------------------------------------------------------------------
__device__ __forceinline__ void red_v4(float* p, float4 v) {
    asm volatile("red.global.add.v4.f32 [%0], {%1, %2, %3, %4};"
                 :: "l"(p), "f"(v.x), "f"(v.y), "f"(v.z), "f"(v.w)
                 : "memory");
}
__device__ __forceinline__ void red_v2(float* p, float2 v) {
    asm volatile("red.global.add.v2.f32 [%0], {%1, %2};"
                 :: "l"(p), "f"(v.x), "f"(v.y)
                 : "memory");
}

__global__ void edge_kernel(const int* __restrict__ edge_src,
                            const int* __restrict__ edge_dst,
                            int E) {
    int idx = blockIdx.x * blockDim.x + threadIdx.x;
    int total = T_TYPES * E;
    if (idx >= total) return;
    int t = idx / E;
    int e = idx - t * E;
    int s = __ldg(&edge_src[(size_t)t * E + e]);
    int d = __ldg(&edge_dst[(size_t)t * E + e]);
    const float* src = g_src_feat + (size_t)s * TUP + t * U_PAD;   // 16B-aligned
    float*       dst = g_agg      + (size_t)d * TUP + t * U_PAD;   // 16B-aligned
    float4 a = __ldg(reinterpret_cast<const float4*>(src));
    float4 b = __ldg(reinterpret_cast<const float4*>(src + 4));
    float2 c = __ldg(reinterpret_cast<const float2*>(src + 8));
    red_v4(dst, a);
    red_v4(dst + 4, b);
    red_v2(dst + 8, c);
}

// ---------------------------------------------------------------------------
// K3a: attention + combine.  FOUR lanes per dst node (lane&3 == t).
// ---------------------------------------------------------------------------
__global__ void __launch_bounds__(256)
combine_kernel(const float* __restrict__ s1,    // [T,U,A]
               const float* __restrict__ s2,    // [T,A,1]
               int n_dst)
{
    __shared__ float s1_s[T_TYPES * U_DIM * DIM_A];   // 800 floats
    __shared__ float s2_s[T_TYPES * DIM_A];           // 80 floats

    int tid = threadIdx.x;
    for (int i = tid; i < T_TYPES * U_DIM * DIM_A; i += 256) s1_s[i] = __ldg(&s1[i]);
    if (tid < T_TYPES * DIM_A) s2_s[tid] = __ldg(&s2[tid]);
    __syncthreads();

    int gidx = blockIdx.x * blockDim.x + tid;
    int j = gidx >> 2;          // node
    int t = gidx & 3;           // edge type (lane&3 == t since blockDim%4==0)
    if (j >= n_dst) return;

    // load this lane's nte[t] row: 3 x float4 (48B aligned)
    float nte[12];
    {
        const float4* p = reinterpret_cast<const float4*>(
            g_agg + (size_t)j * TUP + t * U_PAD);
#pragma unroll
        for (int q = 0; q < 3; q++) {
            float4 v = p[q];
            nte[4 * q] = v.x; nte[4 * q + 1] = v.y;
            nte[4 * q + 2] = v.z; nte[4 * q + 3] = v.w;
        }
    }

    float score = 0.0f;
#pragma unroll
    for (int a = 0; a < DIM_A; a++) {
        float h = 0.0f;
#pragma unroll
        for (int u = 0; u < U_DIM; u++)
            h += nte[u] * s1_s[(t * U_DIM + u) * DIM_A + a];
        score += tanhf(h) * s2_s[t * DIM_A + a];
    }

    // softmax across the 4 lanes of this node
    float m = score;
    m = fmaxf(m, __shfl_xor_sync(0xffffffffu, m, 1));
    m = fmaxf(m, __shfl_xor_sync(0xffffffffu, m, 2));
    float ex = expf(score - m);
    float sum = ex;
    sum += __shfl_xor_sync(0xffffffffu, sum, 1);
    sum += __shfl_xor_sync(0xffffffffu, sum, 2);
    float att = ex / sum;

    // comb[u] = sum_t att[t] * nte[t][u]  (reduce across the 4 lanes)
    float comb[U_DIM];
#pragma unroll
    for (int u = 0; u < U_DIM; u++) {
        float v = att * nte[u];
        v += __shfl_xor_sync(0xffffffffu, v, 1);
        v += __shfl_xor_sync(0xffffffffu, v, 2);
        comb[u] = v;
    }
    if (t == 0) {
        float2* o = reinterpret_cast<float2*>(g_comb + (size_t)j * U_DIM);
#pragma unroll
        for (int q = 0; q < 5; q++)
            o[q] = make_float2(comb[2 * q], comb[2 * q + 1]);
    }
}

// ---------------------------------------------------------------------------
// K3b: projection + normalize.  One warp per 4 (b) rows, fixed t per block.
//      W[t] slice held in registers (7 slices x 10 u).
// ---------------------------------------------------------------------------
__global__ void __launch_bounds__(256, 2)
project_kernel(const int*   __restrict__ output_nodes,
               const float* __restrict__ node_emb,
               const float* __restrict__ W,      // [T,U,EMB]
               float* __restrict__ out,          // [B,T,EMB]
               int n_dst)
{
    int t    = blockIdx.y;
    int lane = threadIdx.x & 31;
    int w    = threadIdx.x >> 5;          // 8 warps
    int b0   = blockIdx.x * 32 + w * 4;   // 4 rows per warp

    // W registers for this t: Wr[it][u] = W[t][u][it*32+lane]
    float Wr[NSLICE][U_DIM];
#pragma unroll
    for (int it = 0; it < NSLICE; it++) {
        int e = it * 32 + lane;
#pragma unroll
        for (int u = 0; u < U_DIM; u++)
            Wr[it][u] = (e < EMB) ? __ldg(&W[(size_t)(t * U_DIM + u) * EMB + e]) : 0.0f;
    }

#pragma unroll
    for (int jj = 0; jj < 4; jj++) {
        int b = b0 + jj;
        if (b >= n_dst) continue;

        float c[U_DIM];
#pragma unroll
        for (int u = 0; u < U_DIM; u++)
            c[u] = __ldg(&g_comb[(size_t)b * U_DIM + u]);   // broadcast

        int node = __ldg(&output_nodes[b]);
        const float* base = node_emb + (size_t)node * EMB;

        float v[NSLICE];
        float ssq = 0.0f;
#pragma unroll
        for (int it = 0; it < NSLICE; it++) {
            int e = it * 32 + lane;
            float val = 0.0f;
            if (e < EMB) {
                val = __ldg(&base[e]);
#pragma unroll
                for (int u = 0; u < U_DIM; u++)
                    val += c[u] * Wr[it][u];
            }
            v[it] = val;
            ssq += val * val;
        }
#pragma unroll
        for (int off = 16; off > 0; off >>= 1)
            ssq += __shfl_xor_sync(0xffffffffu, ssq, off);
        float inv = 1.0f / fmaxf(sqrtf(ssq), 1e-12f);

        float* o = out + ((size_t)b * T_TYPES + t) * EMB;
#pragma unroll
        for (int it = 0; it < NSLICE; it++) {
            int e = it * 32 + lane;
            if (e < EMB) o[e] = v[it] * inv;
        }
    }
}

// ---------------------------------------------------------------------------
// Launch
// ---------------------------------------------------------------------------
extern "C" void kernel_launch(void* const* d_in, const int* in_sizes, int n_in,
                              void* d_out, int out_size) {
    const int*   input_nodes  = (const int*)  d_in[0];
    const int*   output_nodes = (const int*)  d_in[1];
    const int*   edge_src     = (const int*)  d_in[2];
    const int*   edge_dst     = (const int*)  d_in[3];
    const float* node_emb     = (const float*)d_in[4];
    const float* nte_table    = (const float*)d_in[5];
    const float* W            = (const float*)d_in[6];
    const float* s1           = (const float*)d_in[7];
    const float* s2           = (const float*)d_in[8];
    float* out = (float*)d_out;

    int n_src = in_sizes[0];
    int n_dst = in_sizes[1];
    int E     = in_sizes[2] / T_TYPES;

    // K1: gather (one thread per (s,t)) + zero agg
    {
        int n_zero4 = (n_dst * TUP) / 4;
        int n = n_src * T_TYPES;
        int nthreads = n > n_zero4 ? n : n_zero4;
        gather_kernel<<<(nthreads + 255) / 256, 256>>>(input_nodes, nte_table,
                                                       n_src, n_zero4);
    }
    // K2: scatter-add over edges (vector reds)
    {
        int n = T_TYPES * E;
        edge_kernel<<<(n + 255) / 256, 256>>>(edge_src, edge_dst, E);
    }
    // K3a: attention + combine (4 lanes per node)
    {
        int n = n_dst * T_TYPES;
        combine_kernel<<<(n + 255) / 256, 256>>>(s1, s2, n_dst);
    }
    // K3b: projection + normalize
    {
        dim3 grid((n_dst + 31) / 32, T_TYPES);
        project_kernel<<<grid, 256>>>(output_nodes, node_emb, W, out, n_dst);
    }
}